// round 5
// baseline (speedup 1.0000x reference)
#include <cuda_runtime.h>

// Problem constants
#define Bb 2
#define Hh 8
#define NCC 32
#define CC 64
#define OO 2
#define DD 128
#define BH (Bb*Hh)              // 16
#define NTILES (BH*NCC)         // 512
#define TILE_STRIDE (CC*OO*DD)  // 16384
#define OUT_ELEMS (NTILES*TILE_STRIDE) // 8388608
#define GRID 152

// Per-chunk recurrent states h0: states[bh*NC+n][128][128] (d-major)
__device__ float g_states[NTILES * DD * DD];   // 33.5 MB static scratch
__device__ int   g_sync[NTILES + 1];           // [0..512) ready flags, [512] ticket

#define CHAIN_SMEM_FLOATS (128*129 + 768 + 256 + 128 + 8)
#define SMEM_BYTES (CHAIN_SMEM_FLOATS * 4)

// ---------------------------------------------------------------------------
// Chain role: blocks 0..15, sequential over 32 chunks, publishes per-chunk h0.
// ---------------------------------------------------------------------------
__device__ __forceinline__ void chain_role(
    int bh, const float* __restrict__ q, const float* __restrict__ w,
    const float* __restrict__ u, const float* __restrict__ a,
    const float* __restrict__ init, int lin, float* __restrict__ dout,
    float* sm)
{
    float* Hs   = sm;               // 128*129
    float* V    = Hs + 128*129;     // 6*128: w0,w1,u0,u1,a0,a1
    float* kth  = V + 768;          // 2*128
    float* rn   = kth + 256;        // 128
    float* ssww = rn + 128;         // 1
    float* vw0 = V;        float* vw1 = V + 128;
    float* vu0 = V + 256;  float* vu1 = V + 384;
    float* va0 = V + 512;  float* va1 = V + 640;

    const int t = threadIdx.x;

    // Preamble: init state -> smem + publish chunk-0 state
    const float* ip = init + bh * (DD*DD);
    float* sp0 = g_states + (size_t)(bh * NCC) * (DD*DD);
    for (int k = t; k < DD*DD; k += 1024) {
        float v = ip[k];
        Hs[(k >> 7) * 129 + (k & 127)] = v;
        sp0[k] = v;
    }
    __syncthreads();
    if (t == 0) { __threadfence(); atomicExch(&g_sync[bh*NCC], 1); }

    for (int n = 0; n < NCC; n++) {
        const int base = ((bh * NCC + n) * CC + (CC - 1)) * (OO * DD);
        if (t < 768) {
            const int v = t >> 7, d = t & 127;
            const float* src = (v < 2) ? w : ((v < 4) ? u : a);
            V[v*128 + d] = src[base + (v & 1) * DD + d];
        }
        __syncthreads();

        // warp0: sww = w1.w0 ; all: kth0/kth1 in one H pass
        if (t < 32) {
            float s = 0.f;
            #pragma unroll
            for (int i = 0; i < 4; i++) s += vw0[t + 32*i] * vw1[t + 32*i];
            #pragma unroll
            for (int o = 16; o; o >>= 1) s += __shfl_xor_sync(0xffffffffu, s, o);
            if (t == 0) *ssww = s;
        }
        {
            const int p = t & 7, e = t >> 3;       // 128 e x 8 partners
            float s0 = 0.f, s1 = 0.f;
            #pragma unroll
            for (int i = 0; i < 16; i++) {
                const int d = p + 8*i;
                const float h = Hs[d*129 + e];
                s0 = fmaf(vw0[d], h, s0);
                s1 = fmaf(vw1[d], h, s1);
            }
            s0 += __shfl_xor_sync(0xffffffffu, s0, 1);
            s0 += __shfl_xor_sync(0xffffffffu, s0, 2);
            s0 += __shfl_xor_sync(0xffffffffu, s0, 4);
            s1 += __shfl_xor_sync(0xffffffffu, s1, 1);
            s1 += __shfl_xor_sync(0xffffffffu, s1, 2);
            s1 += __shfl_xor_sync(0xffffffffu, s1, 4);
            if (p == 0) { kth[e] = s0; kth[128 + e] = s1; }
        }
        __syncthreads();

        // Update: H' = cA*H + cB*w0[d] + cC*w1[d]
        {
            const int e = t & 127, d0 = t >> 7;
            const float sww = *ssww;
            const float uv0 = vu0[e] - kth[e];
            const float uv1 = vu1[e] - va0[e]*kth[128 + e] - sww*uv0;
            const float cA = va0[e] * va1[e];
            const float cB = uv0 * va1[e];
            const float cC = uv1;
            #pragma unroll
            for (int i = 0; i < 16; i++) {
                const int d = d0 + 8*i;
                float h = Hs[d*129 + e];
                Hs[d*129 + e] = fmaf(h, cA, fmaf(vw0[d], cB, vw1[d]*cC));
            }
        }
        __syncthreads();

        float* dst = (n < NCC-1) ? (g_states + (size_t)(bh*NCC + n + 1) * (DD*DD))
                                 : (dout + OUT_ELEMS + bh * (DD*DD));

        if (!lin) {
            // Row norms (per d over e)
            {
                const int r = t >> 3, p = t & 7;
                float s = 0.f;
                #pragma unroll
                for (int i = 0; i < 16; i++) {
                    float v = Hs[r*129 + p + 8*i];
                    s = fmaf(v, v, s);
                }
                s += __shfl_xor_sync(0xffffffffu, s, 1);
                s += __shfl_xor_sync(0xffffffffu, s, 2);
                s += __shfl_xor_sync(0xffffffffu, s, 4);
                if (p == 0) rn[r] = __fdividef(2.f, sqrtf(s) + 1e-6f);
            }
            __syncthreads();
            // gelu + publish fused: 0.25*x*z*(1+tanh(i)) = 0.5*x*z/(1+exp(-2i))
            {
                const int e = t & 127, d0 = t >> 7;
                #pragma unroll
                for (int i = 0; i < 16; i++) {
                    const int d = d0 + 8*i;
                    float x = Hs[d*129 + e];
                    float z = x * rn[d];
                    float inner = 0.7978845608028654f * fmaf(0.044715f*z*z, z, z);
                    float ex = __expf(-2.f * inner);
                    float val = __fdividef(0.5f * x * z, 1.f + ex);
                    Hs[d*129 + e] = val;
                    dst[d*128 + e] = val;
                }
            }
        } else {
            const int e = t & 127, d0 = t >> 7;
            #pragma unroll
            for (int i = 0; i < 16; i++) {
                const int d = d0 + 8*i;
                dst[d*128 + e] = Hs[d*129 + e];
            }
        }
        __syncthreads();
        if (t == 0 && n < NCC-1) {
            __threadfence(); atomicExch(&g_sync[bh*NCC + n + 1], 1);
        }
    }
}

// ---------------------------------------------------------------------------
// Consumer: one tile per call. warp = c (2 passes: c = wp, wp+32),
// lane = 4 e-columns (e = 4*lane). No smem: av uniform LDG, bv/epilogue coalesced.
// ---------------------------------------------------------------------------
__device__ __forceinline__ void consume_tile(
    int tile, const float* __restrict__ q, const float* __restrict__ w,
    const float* __restrict__ u, const float* __restrict__ a,
    float* __restrict__ dout)
{
    const int t = threadIdx.x;
    const int base = tile * TILE_STRIDE;

    // Acquire this chunk's state
    if (t == 0) {
        while (atomicAdd(&g_sync[tile], 0) == 0) __nanosleep(64);
        __threadfence();
    }
    __syncthreads();

    const int wp = t >> 5, l = t & 31;
    const float* Hl = g_states + (size_t)tile * (DD*DD) + l*4;

    #pragma unroll 1
    for (int cp = 0; cp < 2; cp++) {
        const int c = wp + 32*cp;
        const float* qc = q + base + c*(OO*DD);
        const float* wc = w + base + c*(OO*DD);
        const float* uc = u + base + c*(OO*DD);
        const float* ac = a + base + c*(OO*DD);

        // Per-position scalars sww = w1.w0, sqw = q1.w0 (lane-parallel dot)
        float4 w0l = *(const float4*)(wc + l*4);
        float4 w1l = *(const float4*)(wc + DD + l*4);
        float4 q1l = *(const float4*)(qc + DD + l*4);
        float sw = fmaf(w1l.x, w0l.x, fmaf(w1l.y, w0l.y, fmaf(w1l.z, w0l.z, w1l.w*w0l.w)));
        float sq = fmaf(q1l.x, w0l.x, fmaf(q1l.y, w0l.y, fmaf(q1l.z, w0l.z, q1l.w*w0l.w)));
        #pragma unroll
        for (int o = 16; o; o >>= 1) {
            sw += __shfl_xor_sync(0xffffffffu, sw, o);
            sq += __shfl_xor_sync(0xffffffffu, sq, o);
        }

        // GEMM: acc[type][e], type {0:q0,1:w0,2:q1,3:w1}, e = 4l..4l+3
        float acc[4][4];
        #pragma unroll
        for (int v = 0; v < 4; v++)
            #pragma unroll
            for (int e = 0; e < 4; e++) acc[v][e] = 0.f;

        #pragma unroll 2
        for (int db = 0; db < DD; db += 4) {
            const float4 aq0 = *(const float4*)(qc + db);        // warp-uniform
            const float4 aw0 = *(const float4*)(wc + db);
            const float4 aq1 = *(const float4*)(qc + DD + db);
            const float4 aw1 = *(const float4*)(wc + DD + db);
            const float aq0s[4] = {aq0.x, aq0.y, aq0.z, aq0.w};
            const float aw0s[4] = {aw0.x, aw0.y, aw0.z, aw0.w};
            const float aq1s[4] = {aq1.x, aq1.y, aq1.z, aq1.w};
            const float aw1s[4] = {aw1.x, aw1.y, aw1.z, aw1.w};
            #pragma unroll
            for (int dd = 0; dd < 4; dd++) {
                const float4 hv = *(const float4*)(Hl + (db + dd)*DD);
                const float h[4] = {hv.x, hv.y, hv.z, hv.w};
                #pragma unroll
                for (int e = 0; e < 4; e++) {
                    acc[0][e] = fmaf(aq0s[dd], h[e], acc[0][e]);
                    acc[1][e] = fmaf(aw0s[dd], h[e], acc[1][e]);
                    acc[2][e] = fmaf(aq1s[dd], h[e], acc[2][e]);
                    acc[3][e] = fmaf(aw1s[dd], h[e], acc[3][e]);
                }
            }
        }

        // Epilogue for (c, e = 4l..4l+3); q1l already holds q1[e]
        const float4 q0e = *(const float4*)(qc + l*4);
        const float4 u0e = *(const float4*)(uc + l*4);
        const float4 a0e = *(const float4*)(ac + l*4);
        const float4 u1e = *(const float4*)(uc + DD + l*4);
        const float q0s[4] = {q0e.x, q0e.y, q0e.z, q0e.w};
        const float u0s[4] = {u0e.x, u0e.y, u0e.z, u0e.w};
        const float a0s[4] = {a0e.x, a0e.y, a0e.z, a0e.w};
        const float q1s[4] = {q1l.x, q1l.y, q1l.z, q1l.w};
        const float u1s[4] = {u1e.x, u1e.y, u1e.z, u1e.w};
        float o0[4], o1[4];
        #pragma unroll
        for (int e = 0; e < 4; e++) {
            float uv0  = u0s[e] - acc[1][e];
            o0[e]      = fmaf(q0s[e], uv0, acc[0][e]);
            float kth1 = fmaf(sw, uv0, a0s[e]*acc[3][e]);
            float uv1  = u1s[e] - kth1;
            float oi1  = fmaf(sq, uv0, a0s[e]*acc[2][e]);
            o1[e]      = fmaf(q1s[e], uv1, oi1);
        }
        *(float4*)(dout + base + c*(OO*DD) + l*4)      = make_float4(o0[0], o0[1], o0[2], o0[3]);
        *(float4*)(dout + base + c*(OO*DD) + DD + l*4) = make_float4(o1[0], o1[1], o1[2], o1[3]);
    }
}

// ---------------------------------------------------------------------------

__global__ __launch_bounds__(1024, 1) void fused_kernel(
    const float* __restrict__ q, const float* __restrict__ w,
    const float* __restrict__ u, const float* __restrict__ a,
    const float* __restrict__ init, const int* __restrict__ linflag,
    float* __restrict__ dout)
{
    extern __shared__ float sm[];
    const int b = blockIdx.x;

    if (b < BH)
        chain_role(b, q, w, u, a, init, *linflag, dout, sm);

    // Persistent consumer loop (all blocks, chunk-major ticket order)
    __shared__ int sj;
    for (;;) {
        if (threadIdx.x == 0) sj = atomicAdd(&g_sync[NTILES], 1);
        __syncthreads();
        const int j = sj;
        if (j >= NTILES) break;
        const int n = j >> 4, bh = j & 15;       // chunk-major = production order
        consume_tile(bh * NCC + n, q, w, u, a, dout);
        __syncthreads();
    }
}

extern "C" void kernel_launch(void* const* d_in, const int* in_sizes, int n_in,
                              void* d_out, int out_size) {
    const float* q    = (const float*)d_in[0];
    const float* w    = (const float*)d_in[1];
    const float* u    = (const float*)d_in[2];
    const float* a    = (const float*)d_in[3];
    const float* init = (const float*)d_in[4];
    const int*   lin  = (const int*)d_in[5];
    float* out = (float*)d_out;

    // Reset flags + ticket every launch (graph-capturable memset)
    void* syncptr = nullptr;
    cudaGetSymbolAddress(&syncptr, g_sync);
    cudaMemsetAsync(syncptr, 0, (NTILES + 1) * sizeof(int));

    cudaFuncSetAttribute(fused_kernel, cudaFuncAttributeMaxDynamicSharedMemorySize, SMEM_BYTES);
    fused_kernel<<<GRID, 1024, SMEM_BYTES>>>(q, w, u, a, init, lin, out);
}

// round 7
// speedup vs baseline: 1.0253x; 1.0253x over previous
#include <cuda_runtime.h>
#include <cuda_bf16.h>
#include <cstdint>

// Problem constants
#define Bb 2
#define Hh 8
#define NCC 32
#define CC 64
#define OO 2
#define DD 128
#define BH (Bb*Hh)              // 16
#define NTILES (BH*NCC)         // 512
#define TILE_STRIDE (CC*OO*DD)  // 16384
#define OUT_ELEMS (NTILES*TILE_STRIDE) // 8388608
#define GRID 148

// Per-chunk recurrent states, TRANSPOSED (e-major) bf16 hi/lo split
__device__ __nv_bfloat16 g_hhi[(size_t)NTILES * DD * DD];
__device__ __nv_bfloat16 g_hlo[(size_t)NTILES * DD * DD];
__device__ int g_sync[NTILES + 1];  // [0..512) ready flags, [512] ticket

// ---- SMEM layout (bytes). Row pitch 272 = 17*16B (odd 16B units -> ldmatrix
// conflict-free across 8 consecutive rows). 128 rows per operand tile.
#define PB     272
#define A_HI   0
#define A_LO   34816
#define B_HI   69632
#define B_LO   104448
#define D_OFF  139264
#define DPITCH 132                           // floats
#define CTRL_OFF (D_OFF + 128*DPITCH*4)      // 139264 + 67584 = 206848
#define SMEM_BYTES (CTRL_OFF + 32)

static __device__ __forceinline__ uint32_t smem_u32(const void* p) {
    uint32_t a;
    asm("{ .reg .u64 t; cvta.to.shared.u64 t, %1; cvt.u32.u64 %0, t; }" : "=r"(a) : "l"(p));
    return a;
}
static __device__ __forceinline__ void ldsm4(uint32_t* r, uint32_t addr) {
    asm volatile("ldmatrix.sync.aligned.m8n8.x4.shared.b16 {%0,%1,%2,%3}, [%4];"
        : "=r"(r[0]), "=r"(r[1]), "=r"(r[2]), "=r"(r[3]) : "r"(addr));
}
static __device__ __forceinline__ void mma16816(float* c, const uint32_t* a,
                                                uint32_t b0, uint32_t b1) {
    asm volatile("mma.sync.aligned.m16n8k16.row.col.f32.bf16.bf16.f32 "
        "{%0,%1,%2,%3}, {%4,%5,%6,%7}, {%8,%9}, {%0,%1,%2,%3};"
        : "+f"(c[0]), "+f"(c[1]), "+f"(c[2]), "+f"(c[3])
        : "r"(a[0]), "r"(a[1]), "r"(a[2]), "r"(a[3]), "r"(b0), "r"(b1));
}

// ---------------------------------------------------------------------------
// Chain role (blocks 0..15): per-chunk recurrence; publishes H^T bf16 hi/lo.
// ---------------------------------------------------------------------------
__device__ __forceinline__ void chain_role(
    int bh, const float* __restrict__ q, const float* __restrict__ w,
    const float* __restrict__ u, const float* __restrict__ a,
    const float* __restrict__ init, int lin, float* __restrict__ dout, float* sm)
{
    float* Hs   = sm;               // 128*129
    float* V    = Hs + 128*129;     // 6*128
    float* kth  = V + 768;          // 2*128
    float* rn   = kth + 256;        // 128
    float* ssww = rn + 128;         // 1
    float* vw0 = V;        float* vw1 = V + 128;
    float* vu0 = V + 256;  float* vu1 = V + 384;
    float* va0 = V + 512;  float* va1 = V + 640;
    const int t = threadIdx.x;

    const float* ip = init + bh * (DD*DD);
    for (int k = t; k < DD*DD; k += 1024)
        Hs[(k >> 7) * 129 + (k & 127)] = ip[k];
    __syncthreads();
    // publish tile 0 (transposed, bf16 split)
    {
        __nv_bfloat16* ph = g_hhi + (size_t)(bh*NCC) * (DD*DD);
        __nv_bfloat16* pl = g_hlo + (size_t)(bh*NCC) * (DD*DD);
        const int d = t & 127, e0 = t >> 7;
        #pragma unroll
        for (int i = 0; i < 16; i++) {
            const int e = e0 + 8*i;
            float x = Hs[d*129 + e];
            __nv_bfloat16 hb = __float2bfloat16(x);
            ph[e*128 + d] = hb;
            pl[e*128 + d] = __float2bfloat16(x - __bfloat162float(hb));
        }
    }
    __syncthreads();
    if (t == 0) { __threadfence(); atomicExch(&g_sync[bh*NCC], 1); }

    for (int n = 0; n < NCC; n++) {
        const int base = ((bh * NCC + n) * CC + (CC - 1)) * (OO * DD);
        if (t < 768) {
            const int v = t >> 7, d = t & 127;
            const float* src = (v < 2) ? w : ((v < 4) ? u : a);
            V[v*128 + d] = src[base + (v & 1) * DD + d];
        }
        __syncthreads();

        if (t < 32) {
            float s = 0.f;
            #pragma unroll
            for (int i = 0; i < 4; i++) s += vw0[t + 32*i] * vw1[t + 32*i];
            #pragma unroll
            for (int o = 16; o; o >>= 1) s += __shfl_xor_sync(0xffffffffu, s, o);
            if (t == 0) *ssww = s;
        }
        {
            const int p = t & 7, e = t >> 3;
            float s0 = 0.f, s1 = 0.f;
            #pragma unroll
            for (int i = 0; i < 16; i++) {
                const int d = p + 8*i;
                const float h = Hs[d*129 + e];
                s0 = fmaf(vw0[d], h, s0);
                s1 = fmaf(vw1[d], h, s1);
            }
            s0 += __shfl_xor_sync(0xffffffffu, s0, 1);
            s0 += __shfl_xor_sync(0xffffffffu, s0, 2);
            s0 += __shfl_xor_sync(0xffffffffu, s0, 4);
            s1 += __shfl_xor_sync(0xffffffffu, s1, 1);
            s1 += __shfl_xor_sync(0xffffffffu, s1, 2);
            s1 += __shfl_xor_sync(0xffffffffu, s1, 4);
            if (p == 0) { kth[e] = s0; kth[128 + e] = s1; }
        }
        __syncthreads();

        {
            const int e = t & 127, d0 = t >> 7;
            const float sww = *ssww;
            const float uv0 = vu0[e] - kth[e];
            const float uv1 = vu1[e] - va0[e]*kth[128 + e] - sww*uv0;
            const float cA = va0[e] * va1[e];
            const float cB = uv0 * va1[e];
            const float cC = uv1;
            #pragma unroll
            for (int i = 0; i < 16; i++) {
                const int d = d0 + 8*i;
                float h = Hs[d*129 + e];
                Hs[d*129 + e] = fmaf(h, cA, fmaf(vw0[d], cB, vw1[d]*cC));
            }
        }
        __syncthreads();

        if (!lin) {
            const int r = t >> 3, p = t & 7;
            float s = 0.f;
            #pragma unroll
            for (int i = 0; i < 16; i++) {
                float v = Hs[r*129 + p + 8*i];
                s = fmaf(v, v, s);
            }
            s += __shfl_xor_sync(0xffffffffu, s, 1);
            s += __shfl_xor_sync(0xffffffffu, s, 2);
            s += __shfl_xor_sync(0xffffffffu, s, 4);
            if (p == 0) rn[r] = __fdividef(2.f, sqrtf(s) + 1e-6f);
            __syncthreads();
        }

        // activation (if any) + publish next tile (bf16 T) or h_final (fp32)
        {
            const int d = t & 127, e0 = t >> 7;
            const int last = (n == NCC-1);
            __nv_bfloat16* ph = g_hhi + (size_t)(bh*NCC + n + 1) * (DD*DD);
            __nv_bfloat16* pl = g_hlo + (size_t)(bh*NCC + n + 1) * (DD*DD);
            float* hf = dout + OUT_ELEMS + bh * (DD*DD);
            const float rnd = lin ? 0.f : rn[d];
            #pragma unroll
            for (int i = 0; i < 16; i++) {
                const int e = e0 + 8*i;
                float x = Hs[d*129 + e];
                float val;
                if (!lin) {
                    float z = x * rnd;
                    float inner = 0.7978845608028654f * fmaf(0.044715f*z*z, z, z);
                    float ex = __expf(-2.f * inner);
                    val = __fdividef(0.5f * x * z, 1.f + ex);
                    Hs[d*129 + e] = val;
                } else val = x;
                if (!last) {
                    __nv_bfloat16 hb = __float2bfloat16(val);
                    ph[e*128 + d] = hb;
                    pl[e*128 + d] = __float2bfloat16(val - __bfloat162float(hb));
                } else {
                    hf[d*128 + e] = val;
                }
            }
        }
        __syncthreads();
        if (t == 0 && n < NCC-1) {
            __threadfence(); atomicExch(&g_sync[bh*NCC + n + 1], 1);
        }
    }
}

// ---------------------------------------------------------------------------
// Consumer: mma.sync bf16 GEMM per half-tile (rows = 4 types x 32 c) -> Dsm,
// then fp32 epilogue. 3-term hi/lo split for fp32-grade accuracy.
// ---------------------------------------------------------------------------
__device__ __forceinline__ void consume_tile(
    int tile, const float* __restrict__ q, const float* __restrict__ w,
    const float* __restrict__ u, const float* __restrict__ a,
    float* __restrict__ dout, unsigned char* smem_raw, uint32_t smem_base)
{
    const int t = threadIdx.x;
    const int base = tile * TILE_STRIDE;

    if (t == 0) {
        while (atomicAdd(&g_sync[tile], 0) == 0) __nanosleep(64);
        __threadfence();
    }
    __syncthreads();

    // Stage B = H^T bf16 hi/lo -> smem rows e, pitch PB
    {
        const uint32_t* ph = (const uint32_t*)(g_hhi + (size_t)tile * (DD*DD));
        const uint32_t* pl = (const uint32_t*)(g_hlo + (size_t)tile * (DD*DD));
        #pragma unroll
        for (int i = 0; i < 8; i++) {
            const int p = t + 1024*i;
            const int e = p >> 6, dp = p & 63;
            const uint32_t off = (uint32_t)(e*PB + dp*4);
            *(uint32_t*)(smem_raw + B_HI + off) = ph[p];
            *(uint32_t*)(smem_raw + B_LO + off) = pl[p];
        }
    }

    const int wp = t >> 5, l = t & 31;
    const int lr = l & 7, grp = l >> 3;
    const int mbase = (wp >> 2) * 16;            // m-strip (A rows)
    const int nbase0 = (wp & 3) * 32;            // n-col group (e cols)
    // lane byte offsets inside a tile (add kbase*2 at use)
    const uint32_t aoffA = (uint32_t)((mbase + lr + ((grp & 1) << 3)) * PB + ((grp >> 1) << 3) * 2);
    const uint32_t boffR = (uint32_t)((lr + ((grp >> 1) << 3)) * PB + ((grp & 1) << 3) * 2);

    #pragma unroll 1
    for (int half = 0; half < 2; half++) {
        // Stage A = X rows (v*32+cc), fp32 -> bf16 hi/lo
        #pragma unroll
        for (int i = 0; i < 8; i++) {
            const int p = t + 1024*i;
            const int r = p >> 6, dp = p & 63;
            const int v = r >> 5, cc = r & 31, c = cc + 32*half;
            const float* src = ((v & 1) ? w : q) + base + c*(OO*DD) + (v >> 1)*DD + dp*2;
            const float2 xv = *(const float2*)src;
            __nv_bfloat16 h0 = __float2bfloat16(xv.x);
            __nv_bfloat16 h1 = __float2bfloat16(xv.y);
            __nv_bfloat16 l0 = __float2bfloat16(xv.x - __bfloat162float(h0));
            __nv_bfloat16 l1 = __float2bfloat16(xv.y - __bfloat162float(h1));
            uint32_t hp = (uint32_t)__bfloat16_as_ushort(h0) | ((uint32_t)__bfloat16_as_ushort(h1) << 16);
            uint32_t lp = (uint32_t)__bfloat16_as_ushort(l0) | ((uint32_t)__bfloat16_as_ushort(l1) << 16);
            const uint32_t off = (uint32_t)(r*PB + dp*4);
            *(uint32_t*)(smem_raw + A_HI + off) = hp;
            *(uint32_t*)(smem_raw + A_LO + off) = lp;
        }
        __syncthreads();

        // GEMM: acc[ntile 0..3][4], ntile n = nbase0 + nt*8
        float acc[4][4];
        #pragma unroll
        for (int i = 0; i < 4; i++)
            #pragma unroll
            for (int jj = 0; jj < 4; jj++) acc[i][jj] = 0.f;

        #pragma unroll 1
        for (int k0 = 0; k0 < DD; k0 += 16) {
            uint32_t ah[4], al[4];
            ldsm4(ah, smem_base + A_HI + aoffA + k0*2);
            ldsm4(al, smem_base + A_LO + aoffA + k0*2);
            #pragma unroll
            for (int ntp = 0; ntp < 2; ntp++) {
                const uint32_t bo = (uint32_t)((nbase0 + ntp*16) * PB) + boffR + k0*2;
                uint32_t bhv[4], blv[4];
                ldsm4(bhv, smem_base + B_HI + bo);
                ldsm4(blv, smem_base + B_LO + bo);
                mma16816(acc[ntp*2+0], ah, bhv[0], bhv[1]);
                mma16816(acc[ntp*2+0], ah, blv[0], blv[1]);
                mma16816(acc[ntp*2+0], al, bhv[0], bhv[1]);
                mma16816(acc[ntp*2+1], ah, bhv[2], bhv[3]);
                mma16816(acc[ntp*2+1], ah, blv[2], blv[3]);
                mma16816(acc[ntp*2+1], al, bhv[2], bhv[3]);
            }
        }

        // Write D fragments -> Dsm. Frag: rows mbase + l/4 (+8), cols n + 2*(l%4)
        {
            float* Dsm = (float*)(smem_raw + D_OFF);
            const int r0 = mbase + (l >> 2);
            const int cbase = nbase0 + 2*(l & 3);
            #pragma unroll
            for (int nt = 0; nt < 4; nt++) {
                const int ncol = cbase + nt*8;
                *(float2*)(Dsm + r0*DPITCH + ncol)     = make_float2(acc[nt][0], acc[nt][1]);
                *(float2*)(Dsm + (r0+8)*DPITCH + ncol) = make_float2(acc[nt][2], acc[nt][3]);
            }
        }
        __syncthreads();

        // Epilogue: warp = cc (c = cc+32*half), lane = e/4
        {
            const int cc = wp;
            const int c = cc + 32*half;
            const float* qc = q + base + c*(OO*DD);
            const float* wc = w + base + c*(OO*DD);
            const float* uc = u + base + c*(OO*DD);
            const float* ac = a + base + c*(OO*DD);

            // per-c scalars sww = w1.w0, sqw = q1.w0 (fp32, lane-parallel)
            float4 w0l = *(const float4*)(wc + l*4);
            float4 w1l = *(const float4*)(wc + DD + l*4);
            float4 q1l = *(const float4*)(qc + DD + l*4);
            float sw = fmaf(w1l.x, w0l.x, fmaf(w1l.y, w0l.y, fmaf(w1l.z, w0l.z, w1l.w*w0l.w)));
            float sq = fmaf(q1l.x, w0l.x, fmaf(q1l.y, w0l.y, fmaf(q1l.z, w0l.z, q1l.w*w0l.w)));
            #pragma unroll
            for (int o = 16; o; o >>= 1) {
                sw += __shfl_xor_sync(0xffffffffu, sw, o);
                sq += __shfl_xor_sync(0xffffffffu, sq, o);
            }

            const float* Dsm = (const float*)(smem_raw + D_OFF);
            float4 Aq0 = *(const float4*)(Dsm + ( 0 + cc)*DPITCH + 4*l);
            float4 Aw0 = *(const float4*)(Dsm + (32 + cc)*DPITCH + 4*l);
            float4 Aq1 = *(const float4*)(Dsm + (64 + cc)*DPITCH + 4*l);
            float4 Aw1 = *(const float4*)(Dsm + (96 + cc)*DPITCH + 4*l);

            float4 q0e = *(const float4*)(qc + l*4);
            float4 u0e = *(const float4*)(uc + l*4);
            float4 a0e = *(const float4*)(ac + l*4);
            float4 u1e = *(const float4*)(uc + DD + l*4);

            const float aq0[4] = {Aq0.x,Aq0.y,Aq0.z,Aq0.w}, aw0[4] = {Aw0.x,Aw0.y,Aw0.z,Aw0.w};
            const float aq1[4] = {Aq1.x,Aq1.y,Aq1.z,Aq1.w}, aw1[4] = {Aw1.x,Aw1.y,Aw1.z,Aw1.w};
            const float q0s[4] = {q0e.x,q0e.y,q0e.z,q0e.w}, u0s[4] = {u0e.x,u0e.y,u0e.z,u0e.w};
            const float a0s[4] = {a0e.x,a0e.y,a0e.z,a0e.w}, q1s[4] = {q1l.x,q1l.y,q1l.z,q1l.w};
            const float u1s[4] = {u1e.x,u1e.y,u1e.z,u1e.w};
            float o0[4], o1[4];
            #pragma unroll
            for (int e = 0; e < 4; e++) {
                float uv0  = u0s[e] - aw0[e];
                o0[e]      = fmaf(q0s[e], uv0, aq0[e]);
                float kth1 = fmaf(sw, uv0, a0s[e]*aw1[e]);
                float uv1  = u1s[e] - kth1;
                float oi1  = fmaf(sq, uv0, a0s[e]*aq1[e]);
                o1[e]      = fmaf(q1s[e], uv1, oi1);
            }
            *(float4*)(dout + base + c*(OO*DD) + l*4)      = make_float4(o0[0],o0[1],o0[2],o0[3]);
            *(float4*)(dout + base + c*(OO*DD) + DD + l*4) = make_float4(o1[0],o1[1],o1[2],o1[3]);
        }
        __syncthreads();   // before next half restages A / Dsm
    }
}

// ---------------------------------------------------------------------------

__global__ __launch_bounds__(1024, 1) void fused_kernel(
    const float* __restrict__ q, const float* __restrict__ w,
    const float* __restrict__ u, const float* __restrict__ a,
    const float* __restrict__ init, const int* __restrict__ linflag,
    float* __restrict__ dout)
{
    extern __shared__ unsigned char smem_raw[];
    float* smf = (float*)smem_raw;
    const uint32_t smem_base = smem_u32(smem_raw);
    const int t = threadIdx.x;
    const int b = blockIdx.x;

    if (b < BH)
        chain_role(b, q, w, u, a, init, *linflag, dout, smf);

    int* sjp = (int*)(smem_raw + CTRL_OFF);
    for (;;) {
        if (t == 0) *sjp = atomicAdd(&g_sync[NTILES], 1);
        __syncthreads();
        const int j = *sjp;
        __syncthreads();
        if (j >= NTILES) break;
        const int n = j >> 4, bh = j & 15;           // chunk-major = production order
        consume_tile(bh * NCC + n, q, w, u, a, dout, smem_raw, smem_base);
    }
}

extern "C" void kernel_launch(void* const* d_in, const int* in_sizes, int n_in,
                              void* d_out, int out_size) {
    const float* q    = (const float*)d_in[0];
    const float* w    = (const float*)d_in[1];
    const float* u    = (const float*)d_in[2];
    const float* a    = (const float*)d_in[3];
    const float* init = (const float*)d_in[4];
    const int*   lin  = (const int*)d_in[5];
    float* out = (float*)d_out;

    void* syncptr = nullptr;
    cudaGetSymbolAddress(&syncptr, g_sync);
    cudaMemsetAsync(syncptr, 0, (NTILES + 1) * sizeof(int));

    cudaFuncSetAttribute(fused_kernel, cudaFuncAttributeMaxDynamicSharedMemorySize, SMEM_BYTES);
    fused_kernel<<<GRID, 1024, SMEM_BYTES>>>(q, w, u, a, init, lin, out);
}

// round 8
// speedup vs baseline: 1.8322x; 1.7869x over previous
#include <cuda_runtime.h>
#include <cuda_bf16.h>
#include <cstdint>

// Problem constants
#define Bb 2
#define Hh 8
#define NCC 32
#define CC 64
#define OO 2
#define DD 128
#define BH (Bb*Hh)              // 16
#define NTILES (BH*NCC)         // 512
#define TILE_STRIDE (CC*OO*DD)  // 16384
#define OUT_ELEMS (NTILES*TILE_STRIDE) // 8388608
#define GRID 148
#define NCHAINBLK 32            // 16 chains x 2 halves (cluster pairs)

// Per-chunk recurrent states, TRANSPOSED (e-major) bf16 hi/lo split
__device__ __nv_bfloat16 g_hhi[(size_t)NTILES * DD * DD];
__device__ __nv_bfloat16 g_hlo[(size_t)NTILES * DD * DD];
__device__ int g_sync[NTILES + 1];  // [0..512) ready counts (2 = ready), [512] ticket

// ---- Consumer SMEM layout (bytes). Row pitch 272 = 17*16B: ldmatrix conflict-free.
#define PB     272
#define A_HI   0
#define A_LO   34816
#define B_HI   69632
#define B_LO   104448
#define D_OFF  139264
#define DPITCH 132                           // floats
#define CTRL_OFF (D_OFF + 128*DPITCH*4)      // 206848
#define SMEM_BYTES (CTRL_OFF + 32)

// ---- Chain SMEM layout (float offsets). Half state: 128 d x 64 e, pitch 65.
#define HP 65
#define SM_HS    0
#define SM_V     (128*HP)            // 8320: vw0[128] vw1[128] vu0[64] vu1[64] va0[64] va1[64]
#define SM_KPART (SM_V + 512)        // 8832: 2 x 16 x 64
#define SM_KTH   (SM_KPART + 2048)   // 10880: 2 x 64
#define SM_NPART (SM_KTH + 128)      // 11008: 8 x 128
#define SM_NLOC  (SM_NPART + 1024)   // 12032: 128
#define SM_NREM  (SM_NLOC + 128)     // 12160: 128
#define SM_SWW   (SM_NREM + 128)     // 12288

static __device__ __forceinline__ uint32_t smem_u32(const void* p) {
    uint32_t a;
    asm("{ .reg .u64 t; cvta.to.shared.u64 t, %1; cvt.u32.u64 %0, t; }" : "=r"(a) : "l"(p));
    return a;
}
static __device__ __forceinline__ void ldsm4(uint32_t* r, uint32_t addr) {
    asm volatile("ldmatrix.sync.aligned.m8n8.x4.shared.b16 {%0,%1,%2,%3}, [%4];"
        : "=r"(r[0]), "=r"(r[1]), "=r"(r[2]), "=r"(r[3]) : "r"(addr));
}
static __device__ __forceinline__ void mma16816(float* c, const uint32_t* a,
                                                uint32_t b0, uint32_t b1) {
    asm volatile("mma.sync.aligned.m16n8k16.row.col.f32.bf16.bf16.f32 "
        "{%0,%1,%2,%3}, {%4,%5,%6,%7}, {%8,%9}, {%0,%1,%2,%3};"
        : "+f"(c[0]), "+f"(c[1]), "+f"(c[2]), "+f"(c[3])
        : "r"(a[0]), "r"(a[1]), "r"(a[2]), "r"(a[3]), "r"(b0), "r"(b1));
}

// ---------------------------------------------------------------------------
// Chain role: cluster pair per bh. Each half-block owns e in [half*64, half*64+64).
// ---------------------------------------------------------------------------
static __device__ __forceinline__ float load_V(int t, int base, int half,
    const float* __restrict__ w, const float* __restrict__ u, const float* __restrict__ a) {
    if (t < 256) return w[base + t];                       // vw0 | vw1 (DD=128 so contiguous)
    const int idx = t - 256, vec = idx >> 6, e = idx & 63;
    const float* src = (vec < 2) ? u : a;
    return src[base + (vec & 1)*DD + half*64 + e];
}

__device__ __forceinline__ void chain_role(
    int bh, int half, const float* __restrict__ q, const float* __restrict__ w,
    const float* __restrict__ u, const float* __restrict__ a,
    const float* __restrict__ init, int lin, float* __restrict__ dout,
    float* sm, uint32_t smem_base)
{
    float* Hs    = sm + SM_HS;
    float* V     = sm + SM_V;
    float* kpart = sm + SM_KPART;
    float* kth   = sm + SM_KTH;
    float* npart = sm + SM_NPART;
    float* nloc  = sm + SM_NLOC;
    float* nrem  = sm + SM_NREM;
    float* ssww  = sm + SM_SWW;
    const int t = threadIdx.x;
    const uint32_t peer = 1u - (uint32_t)half;     // cluster rank == blockIdx.x & 1 == half

    // Preamble: init half state + V for chunk 0
    const float* ip = init + bh * (DD*DD);
    for (int k = t; k < 128*64; k += 1024) {
        const int d = k >> 6, e = k & 63;
        Hs[d*HP + e] = ip[d*DD + half*64 + e];
    }
    {
        const int base0 = ((bh*NCC + 0)*CC + (CC-1))*(OO*DD);
        if (t < 512) V[t] = load_V(t, base0, half, w, u, a);
    }
    __syncthreads();
    // Publish tile 0 (bf16 T split) + flag
    {
        __nv_bfloat16* ph = g_hhi + (size_t)(bh*NCC) * (DD*DD);
        __nv_bfloat16* pl = g_hlo + (size_t)(bh*NCC) * (DD*DD);
        const int d = t & 127, g = t >> 7;
        #pragma unroll
        for (int i = 0; i < 8; i++) {
            const int e = g + 8*i;
            float x = Hs[d*HP + e];
            __nv_bfloat16 hb = __float2bfloat16(x);
            ph[(half*64 + e)*128 + d] = hb;
            pl[(half*64 + e)*128 + d] = __float2bfloat16(x - __bfloat162float(hb));
        }
    }
    __syncthreads();
    if (t == 0) { __threadfence(); atomicAdd(&g_sync[bh*NCC], 1); }

    for (int n = 0; n < NCC; n++) {
        const int last = (n == NCC-1);

        // ---- kth main (conflict-free) + sww
        if (t < 32) {
            float s = 0.f;
            #pragma unroll
            for (int i = 0; i < 4; i++) s += V[t + 32*i] * V[128 + t + 32*i];
            #pragma unroll
            for (int o = 16; o; o >>= 1) s += __shfl_xor_sync(0xffffffffu, s, o);
            if (t == 0) *ssww = s;
        }
        {
            const int e = t & 63, p = t >> 6;
            float s0 = 0.f, s1 = 0.f;
            #pragma unroll
            for (int i = 0; i < 8; i++) {
                const int d = p + 16*i;
                const float h = Hs[d*HP + e];
                s0 = fmaf(V[d], h, s0);
                s1 = fmaf(V[128 + d], h, s1);
            }
            kpart[p*64 + e] = s0;
            kpart[1024 + p*64 + e] = s1;
        }
        __syncthreads();
        if (t < 128) {
            const int e = t & 63, o = t >> 6;
            const float* kp = kpart + o*1024 + e;
            float s = 0.f;
            #pragma unroll
            for (int p = 0; p < 16; p++) s += kp[p*64];
            kth[o*64 + e] = s;
        }
        __syncthreads();

        // ---- update: H' = cA*H + cB*w0[d] + cC*w1[d]  (coefs inline per thread)
        {
            const int e = t & 63, p = t >> 6;
            const float sww = *ssww;
            const float uv0 = V[256 + e] - kth[e];
            const float uv1 = V[320 + e] - V[384 + e]*kth[64 + e] - sww*uv0;
            const float cA = V[384 + e] * V[448 + e];
            const float cB = uv0 * V[448 + e];
            const float cC = uv1;
            #pragma unroll
            for (int i = 0; i < 8; i++) {
                const int d = p + 16*i;
                Hs[d*HP + e] = fmaf(Hs[d*HP + e], cA, fmaf(V[d], cB, V[128 + d]*cC));
            }
        }
        __syncthreads();

        // ---- prefetch next chunk's V into regs (hidden under norm/act)
        float vpref = 0.f;
        if (!last && t < 512) {
            const int basen = ((bh*NCC + n + 1)*CC + (CC-1))*(OO*DD);
            vpref = load_V(t, basen, half, w, u, a);
        }

        if (!lin) {
            // ---- norm partials over local e (lane-over-d, conflict-free)
            {
                const int d = t & 127, g = t >> 7;
                float s = 0.f;
                #pragma unroll
                for (int i = 0; i < 8; i++) {
                    const float v = Hs[d*HP + g + 8*i];
                    s = fmaf(v, v, s);
                }
                npart[g*128 + d] = s;
            }
            __syncthreads();
            if (t < 128) {
                float s = 0.f;
                #pragma unroll
                for (int g = 0; g < 8; g++) s += npart[g*128 + t];
                nloc[t] = s;
                // DSMEM: deposit my partial into peer's nrem[t]
                const uint32_t myaddr = smem_base + (uint32_t)((SM_NREM + t) * 4);
                asm volatile(
                    "{ .reg .b32 r; mapa.shared::cluster.u32 r, %0, %1; "
                    "st.shared::cluster.f32 [r], %2; }"
                    :: "r"(myaddr), "r"(peer), "f"(s) : "memory");
            }
            asm volatile("barrier.cluster.arrive.aligned;" ::: "memory");
            asm volatile("barrier.cluster.wait.aligned;" ::: "memory");
        }

        // ---- activation + publish (lane-over-d: conflict-free LDS, coalesced STG)
        {
            const int d = t & 127, g = t >> 7;
            float rnv = 0.f;
            if (!lin) rnv = __fdividef(2.f, sqrtf(nloc[d] + nrem[d]) + 1e-6f);
            __nv_bfloat16* ph = g_hhi + (size_t)(bh*NCC + n + 1) * (DD*DD);
            __nv_bfloat16* pl = g_hlo + (size_t)(bh*NCC + n + 1) * (DD*DD);
            float* hf = dout + OUT_ELEMS + bh * (DD*DD);
            #pragma unroll
            for (int i = 0; i < 8; i++) {
                const int e = g + 8*i;
                float x = Hs[d*HP + e];
                float val = x;
                if (!lin) {
                    const float z = x * rnv;
                    const float inner = 0.7978845608028654f * fmaf(0.044715f*z*z, z, z);
                    const float ex = __expf(-2.f * inner);
                    val = __fdividef(0.5f * x * z, 1.f + ex);
                    Hs[d*HP + e] = val;
                }
                if (!last) {
                    __nv_bfloat16 hb = __float2bfloat16(val);
                    ph[(half*64 + e)*128 + d] = hb;
                    pl[(half*64 + e)*128 + d] = __float2bfloat16(val - __bfloat162float(hb));
                } else {
                    hf[d*DD + half*64 + e] = val;
                }
            }
        }
        if (!last && t < 512) V[t] = vpref;
        __syncthreads();
        if (t == 0 && !last) { __threadfence(); atomicAdd(&g_sync[bh*NCC + n + 1], 1); }
    }
}

// ---------------------------------------------------------------------------
// Consumer: mma.sync bf16 GEMM per half-tile (rows = 4 types x 32 c) -> Dsm,
// then fp32 epilogue. 3-term hi/lo split.
// ---------------------------------------------------------------------------
__device__ __forceinline__ void consume_tile(
    int tile, const float* __restrict__ q, const float* __restrict__ w,
    const float* __restrict__ u, const float* __restrict__ a,
    float* __restrict__ dout, unsigned char* smem_raw, uint32_t smem_base)
{
    const int t = threadIdx.x;
    const int base = tile * TILE_STRIDE;

    if (t == 0) {
        while (atomicAdd(&g_sync[tile], 0) < 2) __nanosleep(64);
        __threadfence();
    }
    __syncthreads();

    // Stage B = H^T bf16 hi/lo -> smem rows e, pitch PB
    {
        const uint32_t* ph = (const uint32_t*)(g_hhi + (size_t)tile * (DD*DD));
        const uint32_t* pl = (const uint32_t*)(g_hlo + (size_t)tile * (DD*DD));
        #pragma unroll
        for (int i = 0; i < 8; i++) {
            const int p = t + 1024*i;
            const int e = p >> 6, dp = p & 63;
            const uint32_t off = (uint32_t)(e*PB + dp*4);
            *(uint32_t*)(smem_raw + B_HI + off) = ph[p];
            *(uint32_t*)(smem_raw + B_LO + off) = pl[p];
        }
    }

    const int wp = t >> 5, l = t & 31;
    const int lr = l & 7, grp = l >> 3;
    const int mbase = (wp >> 2) * 16;
    const int nbase0 = (wp & 3) * 32;
    const uint32_t aoffA = (uint32_t)((mbase + lr + ((grp & 1) << 3)) * PB + ((grp >> 1) << 3) * 2);
    const uint32_t boffR = (uint32_t)((lr + ((grp >> 1) << 3)) * PB + ((grp & 1) << 3) * 2);

    #pragma unroll 1
    for (int half = 0; half < 2; half++) {
        #pragma unroll
        for (int i = 0; i < 8; i++) {
            const int p = t + 1024*i;
            const int r = p >> 6, dp = p & 63;
            const int v = r >> 5, cc = r & 31, c = cc + 32*half;
            const float* src = ((v & 1) ? w : q) + base + c*(OO*DD) + (v >> 1)*DD + dp*2;
            const float2 xv = *(const float2*)src;
            __nv_bfloat16 h0 = __float2bfloat16(xv.x);
            __nv_bfloat16 h1 = __float2bfloat16(xv.y);
            __nv_bfloat16 l0 = __float2bfloat16(xv.x - __bfloat162float(h0));
            __nv_bfloat16 l1 = __float2bfloat16(xv.y - __bfloat162float(h1));
            uint32_t hp = (uint32_t)__bfloat16_as_ushort(h0) | ((uint32_t)__bfloat16_as_ushort(h1) << 16);
            uint32_t lp = (uint32_t)__bfloat16_as_ushort(l0) | ((uint32_t)__bfloat16_as_ushort(l1) << 16);
            const uint32_t off = (uint32_t)(r*PB + dp*4);
            *(uint32_t*)(smem_raw + A_HI + off) = hp;
            *(uint32_t*)(smem_raw + A_LO + off) = lp;
        }
        __syncthreads();

        float acc[4][4];
        #pragma unroll
        for (int i = 0; i < 4; i++)
            #pragma unroll
            for (int jj = 0; jj < 4; jj++) acc[i][jj] = 0.f;

        #pragma unroll 1
        for (int k0 = 0; k0 < DD; k0 += 16) {
            uint32_t ah[4], al[4];
            ldsm4(ah, smem_base + A_HI + aoffA + k0*2);
            ldsm4(al, smem_base + A_LO + aoffA + k0*2);
            #pragma unroll
            for (int ntp = 0; ntp < 2; ntp++) {
                const uint32_t bo = (uint32_t)((nbase0 + ntp*16) * PB) + boffR + k0*2;
                uint32_t bhv[4], blv[4];
                ldsm4(bhv, smem_base + B_HI + bo);
                ldsm4(blv, smem_base + B_LO + bo);
                mma16816(acc[ntp*2+0], ah, bhv[0], bhv[1]);
                mma16816(acc[ntp*2+0], ah, blv[0], blv[1]);
                mma16816(acc[ntp*2+0], al, bhv[0], bhv[1]);
                mma16816(acc[ntp*2+1], ah, bhv[2], bhv[3]);
                mma16816(acc[ntp*2+1], ah, blv[2], blv[3]);
                mma16816(acc[ntp*2+1], al, bhv[2], bhv[3]);
            }
        }

        {
            float* Dsm = (float*)(smem_raw + D_OFF);
            const int r0 = mbase + (l >> 2);
            const int cbase = nbase0 + 2*(l & 3);
            #pragma unroll
            for (int nt = 0; nt < 4; nt++) {
                const int ncol = cbase + nt*8;
                *(float2*)(Dsm + r0*DPITCH + ncol)     = make_float2(acc[nt][0], acc[nt][1]);
                *(float2*)(Dsm + (r0+8)*DPITCH + ncol) = make_float2(acc[nt][2], acc[nt][3]);
            }
        }
        __syncthreads();

        {
            const int cc = wp;
            const int c = cc + 32*half;
            const float* qc = q + base + c*(OO*DD);
            const float* wc = w + base + c*(OO*DD);
            const float* uc = u + base + c*(OO*DD);
            const float* ac = a + base + c*(OO*DD);

            float4 w0l = *(const float4*)(wc + l*4);
            float4 w1l = *(const float4*)(wc + DD + l*4);
            float4 q1l = *(const float4*)(qc + DD + l*4);
            float sw = fmaf(w1l.x, w0l.x, fmaf(w1l.y, w0l.y, fmaf(w1l.z, w0l.z, w1l.w*w0l.w)));
            float sq = fmaf(q1l.x, w0l.x, fmaf(q1l.y, w0l.y, fmaf(q1l.z, w0l.z, q1l.w*w0l.w)));
            #pragma unroll
            for (int o = 16; o; o >>= 1) {
                sw += __shfl_xor_sync(0xffffffffu, sw, o);
                sq += __shfl_xor_sync(0xffffffffu, sq, o);
            }

            const float* Dsm = (const float*)(smem_raw + D_OFF);
            float4 Aq0 = *(const float4*)(Dsm + ( 0 + cc)*DPITCH + 4*l);
            float4 Aw0 = *(const float4*)(Dsm + (32 + cc)*DPITCH + 4*l);
            float4 Aq1 = *(const float4*)(Dsm + (64 + cc)*DPITCH + 4*l);
            float4 Aw1 = *(const float4*)(Dsm + (96 + cc)*DPITCH + 4*l);

            float4 q0e = *(const float4*)(qc + l*4);
            float4 u0e = *(const float4*)(uc + l*4);
            float4 a0e = *(const float4*)(ac + l*4);
            float4 u1e = *(const float4*)(uc + DD + l*4);

            const float aq0[4] = {Aq0.x,Aq0.y,Aq0.z,Aq0.w}, aw0[4] = {Aw0.x,Aw0.y,Aw0.z,Aw0.w};
            const float aq1[4] = {Aq1.x,Aq1.y,Aq1.z,Aq1.w}, aw1[4] = {Aw1.x,Aw1.y,Aw1.z,Aw1.w};
            const float q0s[4] = {q0e.x,q0e.y,q0e.z,q0e.w}, u0s[4] = {u0e.x,u0e.y,u0e.z,u0e.w};
            const float a0s[4] = {a0e.x,a0e.y,a0e.z,a0e.w}, q1s[4] = {q1l.x,q1l.y,q1l.z,q1l.w};
            const float u1s[4] = {u1e.x,u1e.y,u1e.z,u1e.w};
            float o0[4], o1[4];
            #pragma unroll
            for (int e = 0; e < 4; e++) {
                float uv0  = u0s[e] - aw0[e];
                o0[e]      = fmaf(q0s[e], uv0, aq0[e]);
                float kth1 = fmaf(sw, uv0, a0s[e]*aw1[e]);
                float uv1  = u1s[e] - kth1;
                float oi1  = fmaf(sq, uv0, a0s[e]*aq1[e]);
                o1[e]      = fmaf(q1s[e], uv1, oi1);
            }
            *(float4*)(dout + base + c*(OO*DD) + l*4)      = make_float4(o0[0],o0[1],o0[2],o0[3]);
            *(float4*)(dout + base + c*(OO*DD) + DD + l*4) = make_float4(o1[0],o1[1],o1[2],o1[3]);
        }
        __syncthreads();
    }
}

// ---------------------------------------------------------------------------

__global__ __launch_bounds__(1024, 1) __cluster_dims__(2, 1, 1) void fused_kernel(
    const float* __restrict__ q, const float* __restrict__ w,
    const float* __restrict__ u, const float* __restrict__ a,
    const float* __restrict__ init, const int* __restrict__ linflag,
    float* __restrict__ dout)
{
    extern __shared__ unsigned char smem_raw[];
    const uint32_t smem_base = smem_u32(smem_raw);
    const int t = threadIdx.x;
    const int b = blockIdx.x;

    if (b < NCHAINBLK)
        chain_role(b >> 1, b & 1, q, w, u, a, init, *linflag, dout,
                   (float*)smem_raw, smem_base);

    int* sjp = (int*)(smem_raw + CTRL_OFF);
    for (;;) {
        if (t == 0) *sjp = atomicAdd(&g_sync[NTILES], 1);
        __syncthreads();
        const int j = *sjp;
        __syncthreads();
        if (j >= NTILES) break;
        const int n = j >> 4, bh = j & 15;           // chunk-major = production order
        consume_tile(bh * NCC + n, q, w, u, a, dout, smem_raw, smem_base);
    }
}

extern "C" void kernel_launch(void* const* d_in, const int* in_sizes, int n_in,
                              void* d_out, int out_size) {
    const float* q    = (const float*)d_in[0];
    const float* w    = (const float*)d_in[1];
    const float* u    = (const float*)d_in[2];
    const float* a    = (const float*)d_in[3];
    const float* init = (const float*)d_in[4];
    const int*   lin  = (const int*)d_in[5];
    float* out = (float*)d_out;

    void* syncptr = nullptr;
    cudaGetSymbolAddress(&syncptr, g_sync);
    cudaMemsetAsync(syncptr, 0, (NTILES + 1) * sizeof(int));

    cudaFuncSetAttribute(fused_kernel, cudaFuncAttributeMaxDynamicSharedMemorySize, SMEM_BYTES);
    fused_kernel<<<GRID, 1024, SMEM_BYTES>>>(q, w, u, a, init, lin, out);
}

// round 9
// speedup vs baseline: 2.0083x; 1.0961x over previous
#include <cuda_runtime.h>
#include <cuda_bf16.h>
#include <cstdint>

// Problem constants
#define Bb 2
#define Hh 8
#define NCC 32
#define CC 64
#define OO 2
#define DD 128
#define BH (Bb*Hh)              // 16
#define NTILES (BH*NCC)         // 512
#define TILE_STRIDE (CC*OO*DD)  // 16384
#define OUT_ELEMS (NTILES*TILE_STRIDE) // 8388608
#define GRID 132                // 33 clusters x 4 = exactly one resident wave
#define NCHAINBLK 64            // 16 chains x 4 quarter-CTAs (cluster-4)

// Per-chunk recurrent states, TRANSPOSED (e-major) bf16 hi/lo split
__device__ __nv_bfloat16 g_hhi[(size_t)NTILES * DD * DD];
__device__ __nv_bfloat16 g_hlo[(size_t)NTILES * DD * DD];
__device__ int g_sync[NTILES + 1];  // [0..512) ready counts (4 = ready), [512] ticket

// ---- Consumer SMEM layout (bytes). Row pitch 272 = 17*16B: ldmatrix conflict-free.
#define PB     272
#define A_HI   0
#define A_LO   34816
#define B_HI   69632
#define B_LO   104448
#define D_OFF  139264
#define DPITCH 132                           // floats
#define CTRL_OFF (D_OFF + 128*DPITCH*4)      // 206848
#define SMEM_BYTES (CTRL_OFF + 32)

// ---- Chain SMEM layout (float offsets). Quarter state: 128 d x 32 e, pitch 33.
#define HP 33
#define SM_HS    0                   // 128*33 = 4224
#define SM_V     4224                // vw0[128] vw1[128] vu0[32] vu1[32] va0[32] va1[32]
#define SM_KTH   (SM_V + 384)        // 2 x 32
#define SM_NPART (SM_KTH + 64)       // 8 x 128
#define SM_NREM  (SM_NPART + 1024)   // 2 parity x 4 rank x 128
#define SM_SWW   (SM_NREM + 1024)    // 1

static __device__ __forceinline__ uint32_t smem_u32(const void* p) {
    uint32_t a;
    asm("{ .reg .u64 t; cvta.to.shared.u64 t, %1; cvt.u32.u64 %0, t; }" : "=r"(a) : "l"(p));
    return a;
}
static __device__ __forceinline__ void ldsm4(uint32_t* r, uint32_t addr) {
    asm volatile("ldmatrix.sync.aligned.m8n8.x4.shared.b16 {%0,%1,%2,%3}, [%4];"
        : "=r"(r[0]), "=r"(r[1]), "=r"(r[2]), "=r"(r[3]) : "r"(addr));
}
static __device__ __forceinline__ void mma16816(float* c, const uint32_t* a,
                                                uint32_t b0, uint32_t b1) {
    asm volatile("mma.sync.aligned.m16n8k16.row.col.f32.bf16.bf16.f32 "
        "{%0,%1,%2,%3}, {%4,%5,%6,%7}, {%8,%9}, {%0,%1,%2,%3};"
        : "+f"(c[0]), "+f"(c[1]), "+f"(c[2]), "+f"(c[3])
        : "r"(a[0]), "r"(a[1]), "r"(a[2]), "r"(a[3]), "r"(b0), "r"(b1));
}

// ---------------------------------------------------------------------------
// Chain role: cluster-4 per bh. Each CTA owns e in [qt*32, qt*32+32).
// ---------------------------------------------------------------------------
static __device__ __forceinline__ float load_V(int t, int base, int qt,
    const float* __restrict__ w, const float* __restrict__ u, const float* __restrict__ a) {
    if (t < 256) return w[base + t];                       // vw0 | vw1 (full d)
    const int idx = t - 256, vec = idx >> 5, e = idx & 31;
    const float* src = (vec < 2) ? u : a;
    return src[base + (vec & 1)*DD + qt*32 + e];
}

__device__ __forceinline__ void chain_role(
    int bh, int qt, const float* __restrict__ q, const float* __restrict__ w,
    const float* __restrict__ u, const float* __restrict__ a,
    const float* __restrict__ init, int lin, float* __restrict__ dout,
    float* sm, uint32_t smem_base)
{
    float* Hs    = sm + SM_HS;
    float* V     = sm + SM_V;
    float* kth   = sm + SM_KTH;
    float* npart = sm + SM_NPART;
    float* nrem  = sm + SM_NREM;
    float* ssww  = sm + SM_SWW;
    const int t = threadIdx.x;

    // Preamble: init quarter state + V for chunk 0
    const float* ip = init + bh * (DD*DD);
    #pragma unroll
    for (int i = 0; i < 4; i++) {
        const int k = t + 1024*i;
        const int d = k >> 5, e = k & 31;
        Hs[d*HP + e] = ip[d*DD + qt*32 + e];
    }
    {
        const int base0 = ((bh*NCC + 0)*CC + (CC-1))*(OO*DD);
        if (t < 384) V[t] = load_V(t, base0, qt, w, u, a);
    }
    __syncthreads();
    // Publish tile 0 (bf16 T split)
    {
        __nv_bfloat16* ph = g_hhi + (size_t)(bh*NCC) * (DD*DD);
        __nv_bfloat16* pl = g_hlo + (size_t)(bh*NCC) * (DD*DD);
        const int d = t & 127, g = t >> 7;
        #pragma unroll
        for (int i = 0; i < 4; i++) {
            const int e = g + 8*i;
            float x = Hs[d*HP + e];
            __nv_bfloat16 hb = __float2bfloat16(x);
            ph[(qt*32 + e)*128 + d] = hb;
            pl[(qt*32 + e)*128 + d] = __float2bfloat16(x - __bfloat162float(hb));
        }
    }
    __syncthreads();
    if (t == 0) { __threadfence(); atomicAdd(&g_sync[bh*NCC], 1); }

    for (int n = 0; n < NCC; n++) {
        const int last = (n == NCC-1);
        const int par = n & 1;

        // ---- kth: one warp per e; sww redundantly in every warp
        {
            const int l = t & 31, e = t >> 5;
            float s0 = 0.f, s1 = 0.f, swp = 0.f;
            #pragma unroll
            for (int i = 0; i < 4; i++) {
                const int d = l + 32*i;
                const float w0 = V[d], w1 = V[128 + d];
                const float h = Hs[d*HP + e];
                s0 = fmaf(w0, h, s0);
                s1 = fmaf(w1, h, s1);
                swp = fmaf(w0, w1, swp);
            }
            #pragma unroll
            for (int o = 16; o; o >>= 1) {
                s0 += __shfl_xor_sync(0xffffffffu, s0, o);
                s1 += __shfl_xor_sync(0xffffffffu, s1, o);
                swp += __shfl_xor_sync(0xffffffffu, swp, o);
            }
            if (l == 0) {
                kth[e] = s0; kth[32 + e] = s1;
                if (e == 0) *ssww = swp;
            }
        }
        __syncthreads();

        // ---- update: H' = cA*H + cB*w0[d] + cC*w1[d]
        {
            const int e = t & 31, dg = t >> 5;
            const float sww = *ssww;
            const float uv0 = V[256 + e] - kth[e];
            const float uv1 = V[288 + e] - V[320 + e]*kth[32 + e] - sww*uv0;
            const float cA = V[320 + e] * V[352 + e];
            const float cB = uv0 * V[352 + e];
            const float cC = uv1;
            #pragma unroll
            for (int i = 0; i < 4; i++) {
                const int d = dg + 32*i;
                Hs[d*HP + e] = fmaf(Hs[d*HP + e], cA, fmaf(V[d], cB, V[128 + d]*cC));
            }
        }
        __syncthreads();

        // ---- prefetch next chunk's V into regs
        float vpref = 0.f;
        if (!last && t < 384) {
            const int basen = ((bh*NCC + n + 1)*CC + (CC-1))*(OO*DD);
            vpref = load_V(t, basen, qt, w, u, a);
        }

        if (!lin) {
            // ---- norm partials over local e (lane-over-d, conflict-free)
            {
                const int d = t & 127, g = t >> 7;
                float s = 0.f;
                #pragma unroll
                for (int i = 0; i < 4; i++) {
                    const float v = Hs[d*HP + g + 8*i];
                    s = fmaf(v, v, s);
                }
                npart[g*128 + d] = s;
            }
            __syncthreads();
            if (t < 128) {
                float s = 0.f;
                #pragma unroll
                for (int g = 0; g < 8; g++) s += npart[g*128 + t];
                // deposit into slot [par][qt][t] of ALL 4 cluster ranks
                const uint32_t myoff = smem_base + (uint32_t)((SM_NREM + par*512 + qt*128 + t) * 4);
                #pragma unroll
                for (int r = 0; r < 4; r++) {
                    asm volatile(
                        "{ .reg .b32 rr; mapa.shared::cluster.u32 rr, %0, %1; "
                        "st.shared::cluster.f32 [rr], %2; }"
                        :: "r"(myoff), "r"((uint32_t)r), "f"(s) : "memory");
                }
            }
            asm volatile("barrier.cluster.arrive.aligned;" ::: "memory");
            asm volatile("barrier.cluster.wait.aligned;" ::: "memory");
        }

        // ---- activation + publish (lane-over-d)
        {
            const int d = t & 127, g = t >> 7;
            float rnv = 0.f;
            if (!lin) {
                const float* nr = nrem + par*512 + d;
                const float sum4 = (nr[0] + nr[128]) + (nr[256] + nr[384]);
                rnv = __fdividef(2.f, sqrtf(sum4) + 1e-6f);
            }
            __nv_bfloat16* ph = g_hhi + (size_t)(bh*NCC + n + 1) * (DD*DD);
            __nv_bfloat16* pl = g_hlo + (size_t)(bh*NCC + n + 1) * (DD*DD);
            float* hf = dout + OUT_ELEMS + bh * (DD*DD);
            #pragma unroll
            for (int i = 0; i < 4; i++) {
                const int e = g + 8*i;
                float x = Hs[d*HP + e];
                float val = x;
                if (!lin) {
                    const float z = x * rnv;
                    const float inner = 0.7978845608028654f * fmaf(0.044715f*z*z, z, z);
                    const float ex = __expf(-2.f * inner);
                    val = __fdividef(0.5f * x * z, 1.f + ex);
                    Hs[d*HP + e] = val;
                }
                if (!last) {
                    __nv_bfloat16 hb = __float2bfloat16(val);
                    ph[(qt*32 + e)*128 + d] = hb;
                    pl[(qt*32 + e)*128 + d] = __float2bfloat16(val - __bfloat162float(hb));
                } else {
                    hf[d*DD + qt*32 + e] = val;
                }
            }
        }
        if (!last && t < 384) V[t] = vpref;
        __syncthreads();
        if (t == 0 && !last) { __threadfence(); atomicAdd(&g_sync[bh*NCC + n + 1], 1); }
    }
}

// ---------------------------------------------------------------------------
// Consumer: mma.sync bf16 GEMM per half-tile (rows = 4 types x 32 c) -> Dsm,
// then fp32 epilogue. 3-term hi/lo split.
// ---------------------------------------------------------------------------
__device__ __forceinline__ void consume_tile(
    int tile, const float* __restrict__ q, const float* __restrict__ w,
    const float* __restrict__ u, const float* __restrict__ a,
    float* __restrict__ dout, unsigned char* smem_raw, uint32_t smem_base)
{
    const int t = threadIdx.x;
    const int base = tile * TILE_STRIDE;

    if (t == 0) {
        while (atomicAdd(&g_sync[tile], 0) < 4) __nanosleep(64);
        __threadfence();
    }
    __syncthreads();

    // Stage B = H^T bf16 hi/lo -> smem rows e, pitch PB
    {
        const uint32_t* ph = (const uint32_t*)(g_hhi + (size_t)tile * (DD*DD));
        const uint32_t* pl = (const uint32_t*)(g_hlo + (size_t)tile * (DD*DD));
        #pragma unroll
        for (int i = 0; i < 8; i++) {
            const int p = t + 1024*i;
            const int e = p >> 6, dp = p & 63;
            const uint32_t off = (uint32_t)(e*PB + dp*4);
            *(uint32_t*)(smem_raw + B_HI + off) = ph[p];
            *(uint32_t*)(smem_raw + B_LO + off) = pl[p];
        }
    }

    const int wp = t >> 5, l = t & 31;
    const int lr = l & 7, grp = l >> 3;
    const int mbase = (wp >> 2) * 16;
    const int nbase0 = (wp & 3) * 32;
    const uint32_t aoffA = (uint32_t)((mbase + lr + ((grp & 1) << 3)) * PB + ((grp >> 1) << 3) * 2);
    const uint32_t boffR = (uint32_t)((lr + ((grp >> 1) << 3)) * PB + ((grp & 1) << 3) * 2);

    #pragma unroll 1
    for (int half = 0; half < 2; half++) {
        #pragma unroll
        for (int i = 0; i < 8; i++) {
            const int p = t + 1024*i;
            const int r = p >> 6, dp = p & 63;
            const int v = r >> 5, cc = r & 31, c = cc + 32*half;
            const float* src = ((v & 1) ? w : q) + base + c*(OO*DD) + (v >> 1)*DD + dp*2;
            const float2 xv = *(const float2*)src;
            __nv_bfloat16 h0 = __float2bfloat16(xv.x);
            __nv_bfloat16 h1 = __float2bfloat16(xv.y);
            __nv_bfloat16 l0 = __float2bfloat16(xv.x - __bfloat162float(h0));
            __nv_bfloat16 l1 = __float2bfloat16(xv.y - __bfloat162float(h1));
            uint32_t hp = (uint32_t)__bfloat16_as_ushort(h0) | ((uint32_t)__bfloat16_as_ushort(h1) << 16);
            uint32_t lp = (uint32_t)__bfloat16_as_ushort(l0) | ((uint32_t)__bfloat16_as_ushort(l1) << 16);
            const uint32_t off = (uint32_t)(r*PB + dp*4);
            *(uint32_t*)(smem_raw + A_HI + off) = hp;
            *(uint32_t*)(smem_raw + A_LO + off) = lp;
        }
        __syncthreads();

        float acc[4][4];
        #pragma unroll
        for (int i = 0; i < 4; i++)
            #pragma unroll
            for (int jj = 0; jj < 4; jj++) acc[i][jj] = 0.f;

        #pragma unroll 1
        for (int k0 = 0; k0 < DD; k0 += 16) {
            uint32_t ah[4], al[4];
            ldsm4(ah, smem_base + A_HI + aoffA + k0*2);
            ldsm4(al, smem_base + A_LO + aoffA + k0*2);
            #pragma unroll
            for (int ntp = 0; ntp < 2; ntp++) {
                const uint32_t bo = (uint32_t)((nbase0 + ntp*16) * PB) + boffR + k0*2;
                uint32_t bhv[4], blv[4];
                ldsm4(bhv, smem_base + B_HI + bo);
                ldsm4(blv, smem_base + B_LO + bo);
                mma16816(acc[ntp*2+0], ah, bhv[0], bhv[1]);
                mma16816(acc[ntp*2+0], ah, blv[0], blv[1]);
                mma16816(acc[ntp*2+0], al, bhv[0], bhv[1]);
                mma16816(acc[ntp*2+1], ah, bhv[2], bhv[3]);
                mma16816(acc[ntp*2+1], ah, blv[2], blv[3]);
                mma16816(acc[ntp*2+1], al, bhv[2], bhv[3]);
            }
        }

        {
            float* Dsm = (float*)(smem_raw + D_OFF);
            const int r0 = mbase + (l >> 2);
            const int cbase = nbase0 + 2*(l & 3);
            #pragma unroll
            for (int nt = 0; nt < 4; nt++) {
                const int ncol = cbase + nt*8;
                *(float2*)(Dsm + r0*DPITCH + ncol)     = make_float2(acc[nt][0], acc[nt][1]);
                *(float2*)(Dsm + (r0+8)*DPITCH + ncol) = make_float2(acc[nt][2], acc[nt][3]);
            }
        }
        __syncthreads();

        {
            const int cc = wp;
            const int c = cc + 32*half;
            const float* qc = q + base + c*(OO*DD);
            const float* wc = w + base + c*(OO*DD);
            const float* uc = u + base + c*(OO*DD);
            const float* ac = a + base + c*(OO*DD);

            float4 w0l = *(const float4*)(wc + l*4);
            float4 w1l = *(const float4*)(wc + DD + l*4);
            float4 q1l = *(const float4*)(qc + DD + l*4);
            float sw = fmaf(w1l.x, w0l.x, fmaf(w1l.y, w0l.y, fmaf(w1l.z, w0l.z, w1l.w*w0l.w)));
            float sq = fmaf(q1l.x, w0l.x, fmaf(q1l.y, w0l.y, fmaf(q1l.z, w0l.z, q1l.w*w0l.w)));
            #pragma unroll
            for (int o = 16; o; o >>= 1) {
                sw += __shfl_xor_sync(0xffffffffu, sw, o);
                sq += __shfl_xor_sync(0xffffffffu, sq, o);
            }

            const float* Dsm = (const float*)(smem_raw + D_OFF);
            float4 Aq0 = *(const float4*)(Dsm + ( 0 + cc)*DPITCH + 4*l);
            float4 Aw0 = *(const float4*)(Dsm + (32 + cc)*DPITCH + 4*l);
            float4 Aq1 = *(const float4*)(Dsm + (64 + cc)*DPITCH + 4*l);
            float4 Aw1 = *(const float4*)(Dsm + (96 + cc)*DPITCH + 4*l);

            float4 q0e = *(const float4*)(qc + l*4);
            float4 u0e = *(const float4*)(uc + l*4);
            float4 a0e = *(const float4*)(ac + l*4);
            float4 u1e = *(const float4*)(uc + DD + l*4);

            const float aq0[4] = {Aq0.x,Aq0.y,Aq0.z,Aq0.w}, aw0[4] = {Aw0.x,Aw0.y,Aw0.z,Aw0.w};
            const float aq1[4] = {Aq1.x,Aq1.y,Aq1.z,Aq1.w}, aw1[4] = {Aw1.x,Aw1.y,Aw1.z,Aw1.w};
            const float q0s[4] = {q0e.x,q0e.y,q0e.z,q0e.w}, u0s[4] = {u0e.x,u0e.y,u0e.z,u0e.w};
            const float a0s[4] = {a0e.x,a0e.y,a0e.z,a0e.w}, q1s[4] = {q1l.x,q1l.y,q1l.z,q1l.w};
            const float u1s[4] = {u1e.x,u1e.y,u1e.z,u1e.w};
            float o0[4], o1[4];
            #pragma unroll
            for (int e = 0; e < 4; e++) {
                float uv0  = u0s[e] - aw0[e];
                o0[e]      = fmaf(q0s[e], uv0, aq0[e]);
                float kth1 = fmaf(sw, uv0, a0s[e]*aw1[e]);
                float uv1  = u1s[e] - kth1;
                float oi1  = fmaf(sq, uv0, a0s[e]*aq1[e]);
                o1[e]      = fmaf(q1s[e], uv1, oi1);
            }
            *(float4*)(dout + base + c*(OO*DD) + l*4)      = make_float4(o0[0],o0[1],o0[2],o0[3]);
            *(float4*)(dout + base + c*(OO*DD) + DD + l*4) = make_float4(o1[0],o1[1],o1[2],o1[3]);
        }
        __syncthreads();
    }
}

// ---------------------------------------------------------------------------

__global__ __launch_bounds__(1024, 1) __cluster_dims__(4, 1, 1) void fused_kernel(
    const float* __restrict__ q, const float* __restrict__ w,
    const float* __restrict__ u, const float* __restrict__ a,
    const float* __restrict__ init, const int* __restrict__ linflag,
    float* __restrict__ dout)
{
    extern __shared__ unsigned char smem_raw[];
    const uint32_t smem_base = smem_u32(smem_raw);
    const int t = threadIdx.x;
    const int b = blockIdx.x;

    if (b < NCHAINBLK)
        chain_role(b >> 2, b & 3, q, w, u, a, init, *linflag, dout,
                   (float*)smem_raw, smem_base);

    int* sjp = (int*)(smem_raw + CTRL_OFF);
    for (;;) {
        if (t == 0) *sjp = atomicAdd(&g_sync[NTILES], 1);
        __syncthreads();
        const int j = *sjp;
        __syncthreads();
        if (j >= NTILES) break;
        const int n = j >> 4, bh = j & 15;           // chunk-major = production order
        consume_tile(bh * NCC + n, q, w, u, a, dout, smem_raw, smem_base);
    }
}

extern "C" void kernel_launch(void* const* d_in, const int* in_sizes, int n_in,
                              void* d_out, int out_size) {
    const float* q    = (const float*)d_in[0];
    const float* w    = (const float*)d_in[1];
    const float* u    = (const float*)d_in[2];
    const float* a    = (const float*)d_in[3];
    const float* init = (const float*)d_in[4];
    const int*   lin  = (const int*)d_in[5];
    float* out = (float*)d_out;

    void* syncptr = nullptr;
    cudaGetSymbolAddress(&syncptr, g_sync);
    cudaMemsetAsync(syncptr, 0, (NTILES + 1) * sizeof(int));

    cudaFuncSetAttribute(fused_kernel, cudaFuncAttributeMaxDynamicSharedMemorySize, SMEM_BYTES);
    fused_kernel<<<GRID, 1024, SMEM_BYTES>>>(q, w, u, a, init, lin, out);
}